// round 5
// baseline (speedup 1.0000x reference)
#include <cuda_runtime.h>
#include <cuda_bf16.h>
#include <cstdint>

// Problem constants
#define PN 8192      // batch rows
#define PC 1024      // feature dim
#define PS 8192      // negatives (sampled)
#define PUNITS 128000

// ---------------- device scratch (static, allocation-free) ----------------
__device__ __nv_bfloat16 g_X[PN * PC];   // inputs in bf16           (16 MB)
__device__ __nv_bfloat16 g_W[PS * PC];   // gathered sampled rows    (16 MB)
__device__ float g_bcorr[PS];            // bias[sampled] - log(E(sampled))
__device__ float g_true[PN];             // corrected true logits
__device__ float g_rowsum[PN];           // sum_s exp(corrected samp logit)

// ---------------- helpers ----------------
__device__ __forceinline__ float neg_log_expected(int id) {
    // E = -expm1(S * log1p(-p)),  p = (log(id+2)-log(id+1)) / log(UNITS+1)
    float idf = (float)id;
    float p = (logf(idf + 2.0f) - logf(idf + 1.0f)) / logf((float)(PUNITS + 1));
    float e = -expm1f((float)PS * log1pf(-p));
    return -logf(e);
}

__device__ __forceinline__ void ldm_x4(uint32_t (&r)[4], uint32_t saddr) {
    asm volatile("ldmatrix.sync.aligned.m8n8.x4.shared.b16 {%0,%1,%2,%3}, [%4];"
                 : "=r"(r[0]), "=r"(r[1]), "=r"(r[2]), "=r"(r[3])
                 : "r"(saddr));
}

__device__ __forceinline__ void mma_bf16(float (&c)[4], const uint32_t (&a)[4],
                                         const uint32_t b0, const uint32_t b1) {
    asm volatile(
        "mma.sync.aligned.m16n8k16.row.col.f32.bf16.bf16.f32 "
        "{%0,%1,%2,%3}, {%4,%5,%6,%7}, {%8,%9}, {%0,%1,%2,%3};"
        : "+f"(c[0]), "+f"(c[1]), "+f"(c[2]), "+f"(c[3])
        : "r"(a[0]), "r"(a[1]), "r"(a[2]), "r"(a[3]), "r"(b0), "r"(b1));
}

// ---------------- prep: bf16 convert inputs + gather sampled W rows ----------------
__global__ void prep_gather_kernel(const float* __restrict__ inputs,
                                   const int* __restrict__ sampled,
                                   const float* __restrict__ kern) {
    const int total4 = (PN * PC) / 4;  // float4 units
    for (int i = blockIdx.x * blockDim.x + threadIdx.x; i < total4;
         i += gridDim.x * blockDim.x) {
        float4 x = ((const float4*)inputs)[i];
        __nv_bfloat162* dx = (__nv_bfloat162*)g_X + (size_t)i * 2;
        dx[0] = __floats2bfloat162_rn(x.x, x.y);
        dx[1] = __floats2bfloat162_rn(x.z, x.w);

        int s  = i >> 8;      // (i*4) / 1024
        int c4 = i & 255;     // float4 index within row
        float4 w = ((const float4*)(kern + ((size_t)sampled[s] << 10)))[c4];
        __nv_bfloat162* dw = (__nv_bfloat162*)g_W + (size_t)i * 2;
        dw[0] = __floats2bfloat162_rn(w.x, w.y);
        dw[1] = __floats2bfloat162_rn(w.z, w.w);
    }
}

// ---------------- prep: sampled bias + correction ----------------
__global__ void prep_bcorr_kernel(const int* __restrict__ sampled,
                                  const float* __restrict__ bias) {
    int s = blockIdx.x * blockDim.x + threadIdx.x;
    if (s < PS) {
        int sid = sampled[s];
        g_bcorr[s] = bias[sid] + neg_log_expected(sid);
    }
}

// ---------------- prep: true logits (fp32) + zero rowsums ----------------
__global__ void prep_true_kernel(const float* __restrict__ inputs,
                                 const int* __restrict__ targets,
                                 const float* __restrict__ kern,
                                 const float* __restrict__ bias) {
    int warp = threadIdx.x >> 5, lane = threadIdx.x & 31;
    int n = blockIdx.x * 8 + warp;
    if (n >= PN) return;
    int tgt = targets[n];
    const float4* xr = (const float4*)(inputs + ((size_t)n << 10));
    const float4* wr = (const float4*)(kern + ((size_t)tgt << 10));
    float d = 0.f;
#pragma unroll
    for (int it = 0; it < 8; ++it) {
        float4 a = xr[lane + it * 32];
        float4 b = wr[lane + it * 32];
        d += a.x * b.x + a.y * b.y + a.z * b.z + a.w * b.w;
    }
#pragma unroll
    for (int o = 16; o; o >>= 1) d += __shfl_down_sync(0xffffffffu, d, o);
    if (lane == 0) {
        g_true[n] = d + bias[tgt] + neg_log_expected(tgt);
        g_rowsum[n] = 0.f;
    }
}

// ---------------- fused GEMM (bf16 mma.sync) + exp epilogue ----------------
// CTA tile 128x128, K-chunk 32, 8 warps in 2(M) x 4(N), warp tile 64x32.
#define SLD 40  // smem K stride in bf16 elems (32 + 8 pad -> conflict-free ldmatrix)

__global__ __launch_bounds__(256, 2) void gemm_exp_kernel(
    const int* __restrict__ targets, const int* __restrict__ sampled) {
    __shared__ __align__(16) __nv_bfloat16 As[128 * SLD];
    __shared__ __align__(16) __nv_bfloat16 Bs[128 * SLD];
    __shared__ float srow[128];

    const int tid = threadIdx.x;
    const int lane = tid & 31, warp = tid >> 5;
    const int wm = warp >> 2, wn = warp & 3;
    const int bm = blockIdx.y * 128, bn = blockIdx.x * 128;

    float acc[4][4][4];
#pragma unroll
    for (int mi = 0; mi < 4; mi++)
#pragma unroll
        for (int ni = 0; ni < 4; ni++)
#pragma unroll
            for (int e = 0; e < 4; e++) acc[mi][ni][e] = 0.f;

    if (tid < 128) srow[tid] = 0.f;

    const uint32_t sA = (uint32_t)__cvta_generic_to_shared(As);
    const uint32_t sB = (uint32_t)__cvta_generic_to_shared(Bs);

    // ldmatrix per-lane address components (within tile)
    const int arow = wm * 64 + (lane & 7) + 8 * ((lane >> 3) & 1);
    const int acoff = (lane >> 4) * 8;
    const int brow = wn * 32 + (lane & 7) + 8 * (lane >> 4);
    const int bcoff = ((lane >> 3) & 1) * 8;

    // global->shared load mapping: 512 16B chunks per operand, 2 per thread
    const int r0 = tid >> 2, s0 = (tid & 3);       // chunk tid
    const int r1 = r0 + 64, s1 = s0;               // chunk tid+256
    const uint4* Ag0 = (const uint4*)(g_X + ((size_t)(bm + r0) << 10));
    const uint4* Ag1 = (const uint4*)(g_X + ((size_t)(bm + r1) << 10));
    const uint4* Bg0 = (const uint4*)(g_W + ((size_t)(bn + r0) << 10));
    const uint4* Bg1 = (const uint4*)(g_W + ((size_t)(bn + r1) << 10));
    uint4* Asd0 = (uint4*)(As + r0 * SLD + s0 * 8);
    uint4* Asd1 = (uint4*)(As + r1 * SLD + s1 * 8);
    uint4* Bsd0 = (uint4*)(Bs + r0 * SLD + s0 * 8);
    uint4* Bsd1 = (uint4*)(Bs + r1 * SLD + s1 * 8);

    for (int kt = 0; kt < PC / 32; ++kt) {
        __syncthreads();
        int gi0 = kt * 4 + s0;
        int gi1 = kt * 4 + s1;
        *Asd0 = Ag0[gi0];
        *Asd1 = Ag1[gi1];
        *Bsd0 = Bg0[gi0];
        *Bsd1 = Bg1[gi1];
        __syncthreads();

#pragma unroll
        for (int ks = 0; ks < 2; ++ks) {
            uint32_t a[4][4];
            uint32_t b[4][2];
#pragma unroll
            for (int mi = 0; mi < 4; mi++) {
                uint32_t addr = sA + (uint32_t)(((arow + mi * 16) * SLD +
                                                 ks * 16 + acoff) * 2);
                ldm_x4(a[mi], addr);
            }
#pragma unroll
            for (int nb = 0; nb < 2; nb++) {
                uint32_t r[4];
                uint32_t addr = sB + (uint32_t)(((brow + nb * 16) * SLD +
                                                 ks * 16 + bcoff) * 2);
                ldm_x4(r, addr);
                b[2 * nb][0] = r[0];
                b[2 * nb][1] = r[1];
                b[2 * nb + 1][0] = r[2];
                b[2 * nb + 1][1] = r[3];
            }
#pragma unroll
            for (int mi = 0; mi < 4; mi++)
#pragma unroll
                for (int ni = 0; ni < 4; ni++)
                    mma_bf16(acc[mi][ni], a[mi], b[ni][0], b[ni][1]);
        }
    }

    // ---- epilogue: corrected logits -> exp -> per-row partial sums ----
    int tg[4][2];
#pragma unroll
    for (int mi = 0; mi < 4; mi++)
#pragma unroll
        for (int h = 0; h < 2; h++)
            tg[mi][h] = targets[bm + wm * 64 + mi * 16 + (lane >> 2) + h * 8];

    float rs[4][2];
#pragma unroll
    for (int mi = 0; mi < 4; mi++) { rs[mi][0] = 0.f; rs[mi][1] = 0.f; }

#pragma unroll
    for (int ni = 0; ni < 4; ni++) {
#pragma unroll
        for (int j = 0; j < 2; j++) {
            int col = bn + wn * 32 + ni * 8 + ((lane & 3) << 1) + j;
            int sid = sampled[col];
            float bc = g_bcorr[col];
#pragma unroll
            for (int mi = 0; mi < 4; mi++) {
#pragma unroll
                for (int h = 0; h < 2; h++) {
                    if (sid != tg[mi][h])
                        rs[mi][h] += expf(acc[mi][ni][h * 2 + j] + bc);
                }
            }
        }
    }

#pragma unroll
    for (int mi = 0; mi < 4; mi++) {
#pragma unroll
        for (int h = 0; h < 2; h++) {
            float v = rs[mi][h];
            v += __shfl_xor_sync(0xffffffffu, v, 1);
            v += __shfl_xor_sync(0xffffffffu, v, 2);
            if ((lane & 3) == 0)
                atomicAdd(&srow[wm * 64 + mi * 16 + (lane >> 2) + h * 8], v);
        }
    }
    __syncthreads();
    if (tid < 128) atomicAdd(&g_rowsum[bm + tid], srow[tid]);
}

// ---------------- finalize: per-example loss + mean ----------------
__global__ void finalize_kernel(float* __restrict__ out) {
    __shared__ double sh[32];
    double local = 0.0;
    for (int n = threadIdx.x; n < PN; n += 1024) {
        float t = g_true[n];
        float v = logf(g_rowsum[n] + expf(t)) - t;
        local += (double)v;
    }
#pragma unroll
    for (int o = 16; o; o >>= 1) local += __shfl_down_sync(0xffffffffu, local, o);
    if ((threadIdx.x & 31) == 0) sh[threadIdx.x >> 5] = local;
    __syncthreads();
    if (threadIdx.x < 32) {
        double v = sh[threadIdx.x];
#pragma unroll
        for (int o = 16; o; o >>= 1) v += __shfl_down_sync(0xffffffffu, v, o);
        if (threadIdx.x == 0) out[0] = (float)(v / (double)PN);
    }
}

// ---------------- entry ----------------
extern "C" void kernel_launch(void* const* d_in, const int* in_sizes, int n_in,
                              void* d_out, int out_size) {
    const float* inputs  = (const float*)d_in[0];
    const int*   targets = (const int*)d_in[1];
    const int*   sampled = (const int*)d_in[2];
    const float* kern    = (const float*)d_in[3];
    const float* bias    = (const float*)d_in[4];
    float* out = (float*)d_out;

    prep_gather_kernel<<<4096, 256>>>(inputs, sampled, kern);
    prep_bcorr_kernel<<<PS / 256, 256>>>(sampled, bias);
    prep_true_kernel<<<PN / 8, 256>>>(inputs, targets, kern, bias);

    dim3 grid(PS / 128, PN / 128);
    gemm_exp_kernel<<<grid, 256>>>(targets, sampled);

    finalize_kernel<<<1, 1024>>>(out);
}

// round 7
// speedup vs baseline: 1.2077x; 1.2077x over previous
#include <cuda_runtime.h>
#include <cuda_bf16.h>
#include <cstdint>

// Problem constants
#define PN 8192      // batch rows
#define PC 1024      // feature dim
#define PS 8192      // negatives (sampled)
#define PUNITS 128000

// ---------------- device scratch (static, allocation-free) ----------------
__device__ __nv_bfloat16 g_X[PN * PC];   // inputs in bf16           (16 MB)
__device__ __nv_bfloat16 g_W[PS * PC];   // gathered sampled rows    (16 MB)
__device__ float g_bcorr[PS];            // bias[sampled] - log(E(sampled))
__device__ float g_true[PN];             // corrected true logits
__device__ float g_rowsum[PN];           // sum_s exp(corrected samp logit)

// ---------------- helpers ----------------
__device__ __forceinline__ float neg_log_expected(int id) {
    float idf = (float)id;
    float p = (logf(idf + 2.0f) - logf(idf + 1.0f)) / logf((float)(PUNITS + 1));
    float e = -expm1f((float)PS * log1pf(-p));
    return -logf(e);
}

__device__ __forceinline__ void ldm_x4(uint32_t (&r)[4], uint32_t saddr) {
    asm volatile("ldmatrix.sync.aligned.m8n8.x4.shared.b16 {%0,%1,%2,%3}, [%4];"
                 : "=r"(r[0]), "=r"(r[1]), "=r"(r[2]), "=r"(r[3])
                 : "r"(saddr));
}

__device__ __forceinline__ void mma_bf16(float (&c)[4], const uint32_t (&a)[4],
                                         const uint32_t b0, const uint32_t b1) {
    asm volatile(
        "mma.sync.aligned.m16n8k16.row.col.f32.bf16.bf16.f32 "
        "{%0,%1,%2,%3}, {%4,%5,%6,%7}, {%8,%9}, {%0,%1,%2,%3};"
        : "+f"(c[0]), "+f"(c[1]), "+f"(c[2]), "+f"(c[3])
        : "r"(a[0]), "r"(a[1]), "r"(a[2]), "r"(a[3]), "r"(b0), "r"(b1));
}

#define CP_ASYNC16(dst, src) \
    asm volatile("cp.async.cg.shared.global [%0], [%1], 16;" :: "r"(dst), "l"(src))

// ---------------- prep: bf16 convert inputs + gather sampled W rows ----------------
__global__ void prep_gather_kernel(const float* __restrict__ inputs,
                                   const int* __restrict__ sampled,
                                   const float* __restrict__ kern) {
    const int total4 = (PN * PC) / 4;  // float4 units
    for (int i = blockIdx.x * blockDim.x + threadIdx.x; i < total4;
         i += gridDim.x * blockDim.x) {
        float4 x = ((const float4*)inputs)[i];
        __nv_bfloat162* dx = (__nv_bfloat162*)g_X + (size_t)i * 2;
        dx[0] = __floats2bfloat162_rn(x.x, x.y);
        dx[1] = __floats2bfloat162_rn(x.z, x.w);

        int s  = i >> 8;      // (i*4) / 1024
        int c4 = i & 255;     // float4 index within row
        float4 w = ((const float4*)(kern + ((size_t)sampled[s] << 10)))[c4];
        __nv_bfloat162* dw = (__nv_bfloat162*)g_W + (size_t)i * 2;
        dw[0] = __floats2bfloat162_rn(w.x, w.y);
        dw[1] = __floats2bfloat162_rn(w.z, w.w);
    }
}

// ---------------- prep: sampled bias + correction ----------------
__global__ void prep_bcorr_kernel(const int* __restrict__ sampled,
                                  const float* __restrict__ bias) {
    int s = blockIdx.x * blockDim.x + threadIdx.x;
    if (s < PS) {
        int sid = sampled[s];
        g_bcorr[s] = bias[sid] + neg_log_expected(sid);
    }
}

// ---------------- prep: true logits (fp32) + zero rowsums ----------------
__global__ void prep_true_kernel(const float* __restrict__ inputs,
                                 const int* __restrict__ targets,
                                 const float* __restrict__ kern,
                                 const float* __restrict__ bias) {
    int warp = threadIdx.x >> 5, lane = threadIdx.x & 31;
    int n = blockIdx.x * 8 + warp;
    if (n >= PN) return;
    int tgt = targets[n];
    const float4* xr = (const float4*)(inputs + ((size_t)n << 10));
    const float4* wr = (const float4*)(kern + ((size_t)tgt << 10));
    float d = 0.f;
#pragma unroll
    for (int it = 0; it < 8; ++it) {
        float4 a = xr[lane + it * 32];
        float4 b = wr[lane + it * 32];
        d += a.x * b.x + a.y * b.y + a.z * b.z + a.w * b.w;
    }
#pragma unroll
    for (int o = 16; o; o >>= 1) d += __shfl_down_sync(0xffffffffu, d, o);
    if (lane == 0) {
        g_true[n] = d + bias[tgt] + neg_log_expected(tgt);
        g_rowsum[n] = 0.f;
    }
}

// ---------------- fused GEMM (bf16 mma.sync, cp.async 4-stage) + exp epilogue ----
// CTA tile 128x128, K-chunk 32, 8 warps in 2(M) x 4(N), warp tile 64x32.
#define SLD 40                         // smem K stride (32 + 8 pad), 80B rows
#define STG_BYTES (128 * SLD * 2)      // 10240 B per operand stage
#define NSTG 4
#define OFF_B    (NSTG * STG_BYTES)    // 40960
#define OFF_SROW (2 * NSTG * STG_BYTES)// 81920
#define SMEM_BYTES (OFF_SROW + 512)
#define NK (PC / 32)                   // 32 K-chunks

__global__ __launch_bounds__(256, 2) void gemm_exp_kernel(
    const int* __restrict__ targets, const int* __restrict__ sampled) {
    extern __shared__ char smem[];
    float* srow = (float*)(smem + OFF_SROW);

    const int tid = threadIdx.x;
    const int lane = tid & 31, warp = tid >> 5;
    const int wm = warp >> 2, wn = warp & 3;
    const int bm = blockIdx.y * 128, bn = blockIdx.x * 128;

    float acc[4][4][4];
#pragma unroll
    for (int mi = 0; mi < 4; mi++)
#pragma unroll
        for (int ni = 0; ni < 4; ni++)
#pragma unroll
            for (int e = 0; e < 4; e++) acc[mi][ni][e] = 0.f;

    if (tid < 128) srow[tid] = 0.f;

    uint32_t sbase;
    asm("{ .reg .u64 t; cvta.to.shared.u64 t, %1; cvt.u32.u64 %0, t; }"
        : "=r"(sbase) : "l"(smem));
    const uint32_t sA = sbase;
    const uint32_t sB = sbase + OFF_B;

    // ldmatrix per-lane address components (within tile)
    const int arow = wm * 64 + (lane & 7) + 8 * ((lane >> 3) & 1);
    const int acoff = (lane >> 4) * 8;
    const int brow = wn * 32 + (lane & 7) + 8 * (lane >> 4);
    const int bcoff = ((lane >> 3) & 1) * 8;

    // global->shared: 512 16B chunks per operand per stage, 2 per thread
    const int r0 = tid >> 2, s0 = tid & 3;
    const int r1 = r0 + 64;
    const __nv_bfloat16* Ag0 = g_X + (size_t)(bm + r0) * PC + s0 * 8;
    const __nv_bfloat16* Ag1 = g_X + (size_t)(bm + r1) * PC + s0 * 8;
    const __nv_bfloat16* Bg0 = g_W + (size_t)(bn + r0) * PC + s0 * 8;
    const __nv_bfloat16* Bg1 = g_W + (size_t)(bn + r1) * PC + s0 * 8;
    const uint32_t dA0 = sA + (uint32_t)(r0 * SLD + s0 * 8) * 2;
    const uint32_t dA1 = sA + (uint32_t)(r1 * SLD + s0 * 8) * 2;
    const uint32_t dB0 = sB + (uint32_t)(r0 * SLD + s0 * 8) * 2;
    const uint32_t dB1 = sB + (uint32_t)(r1 * SLD + s0 * 8) * 2;

#define LOAD_STAGE(kt_)                                                        \
    do {                                                                       \
        if ((kt_) < NK) {                                                      \
            uint32_t so = (uint32_t)((kt_) & 3) * STG_BYTES;                   \
            int ko = (kt_) * 32;                                               \
            CP_ASYNC16(dA0 + so, Ag0 + ko);                                    \
            CP_ASYNC16(dA1 + so, Ag1 + ko);                                    \
            CP_ASYNC16(dB0 + so, Bg0 + ko);                                    \
            CP_ASYNC16(dB1 + so, Bg1 + ko);                                    \
        }                                                                      \
        asm volatile("cp.async.commit_group;" ::: "memory");                   \
    } while (0)

    // prologue: stages 0,1,2 in flight
    LOAD_STAGE(0);
    LOAD_STAGE(1);
    LOAD_STAGE(2);

#pragma unroll 1
    for (int kt = 0; kt < NK; ++kt) {
        asm volatile("cp.async.wait_group 2;" ::: "memory");
        __syncthreads();

        // issue loads for stage kt+3 (overwrites buffer computed at kt-1)
        LOAD_STAGE(kt + 3);

        const uint32_t aoff = (uint32_t)(kt & 3) * STG_BYTES;

#pragma unroll
        for (int ks = 0; ks < 2; ++ks) {
            uint32_t a[4][4];
            uint32_t b[4][2];
#pragma unroll
            for (int mi = 0; mi < 4; mi++) {
                uint32_t addr = sA + aoff +
                    (uint32_t)(((arow + mi * 16) * SLD + ks * 16 + acoff) * 2);
                ldm_x4(a[mi], addr);
            }
#pragma unroll
            for (int nb = 0; nb < 2; nb++) {
                uint32_t r[4];
                uint32_t addr = sB + aoff +
                    (uint32_t)(((brow + nb * 16) * SLD + ks * 16 + bcoff) * 2);
                ldm_x4(r, addr);
                b[2 * nb][0] = r[0];
                b[2 * nb][1] = r[1];
                b[2 * nb + 1][0] = r[2];
                b[2 * nb + 1][1] = r[3];
            }
#pragma unroll
            for (int mi = 0; mi < 4; mi++)
#pragma unroll
                for (int ni = 0; ni < 4; ni++)
                    mma_bf16(acc[mi][ni], a[mi], b[ni][0], b[ni][1]);
        }
    }

    // ---- epilogue: corrected logits -> exp -> per-row partial sums ----
    int tg[4][2];
#pragma unroll
    for (int mi = 0; mi < 4; mi++)
#pragma unroll
        for (int h = 0; h < 2; h++)
            tg[mi][h] = targets[bm + wm * 64 + mi * 16 + (lane >> 2) + h * 8];

    float rs[4][2];
#pragma unroll
    for (int mi = 0; mi < 4; mi++) { rs[mi][0] = 0.f; rs[mi][1] = 0.f; }

#pragma unroll
    for (int ni = 0; ni < 4; ni++) {
#pragma unroll
        for (int j = 0; j < 2; j++) {
            int col = bn + wn * 32 + ni * 8 + ((lane & 3) << 1) + j;
            int sid = sampled[col];
            float bc = g_bcorr[col];
#pragma unroll
            for (int mi = 0; mi < 4; mi++) {
#pragma unroll
                for (int h = 0; h < 2; h++) {
                    if (sid != tg[mi][h])
                        rs[mi][h] += __expf(acc[mi][ni][h * 2 + j] + bc);
                }
            }
        }
    }

#pragma unroll
    for (int mi = 0; mi < 4; mi++) {
#pragma unroll
        for (int h = 0; h < 2; h++) {
            float v = rs[mi][h];
            v += __shfl_xor_sync(0xffffffffu, v, 1);
            v += __shfl_xor_sync(0xffffffffu, v, 2);
            if ((lane & 3) == 0)
                atomicAdd(&srow[wm * 64 + mi * 16 + (lane >> 2) + h * 8], v);
        }
    }
    __syncthreads();
    if (tid < 128) atomicAdd(&g_rowsum[bm + tid], srow[tid]);
}

// ---------------- finalize: per-example loss + mean ----------------
__global__ void finalize_kernel(float* __restrict__ out) {
    __shared__ double sh[32];
    double local = 0.0;
    for (int n = threadIdx.x; n < PN; n += 1024) {
        float t = g_true[n];
        float v = logf(g_rowsum[n] + expf(t)) - t;
        local += (double)v;
    }
#pragma unroll
    for (int o = 16; o; o >>= 1) local += __shfl_down_sync(0xffffffffu, local, o);
    if ((threadIdx.x & 31) == 0) sh[threadIdx.x >> 5] = local;
    __syncthreads();
    if (threadIdx.x < 32) {
        double v = sh[threadIdx.x];
#pragma unroll
        for (int o = 16; o; o >>= 1) v += __shfl_down_sync(0xffffffffu, v, o);
        if (threadIdx.x == 0) out[0] = (float)(v / (double)PN);
    }
}

// ---------------- entry ----------------
extern "C" void kernel_launch(void* const* d_in, const int* in_sizes, int n_in,
                              void* d_out, int out_size) {
    const float* inputs  = (const float*)d_in[0];
    const int*   targets = (const int*)d_in[1];
    const int*   sampled = (const int*)d_in[2];
    const float* kern    = (const float*)d_in[3];
    const float* bias    = (const float*)d_in[4];
    float* out = (float*)d_out;

    static int smem_set = 0;
    if (!smem_set) {
        cudaFuncSetAttribute(gemm_exp_kernel,
                             cudaFuncAttributeMaxDynamicSharedMemorySize, SMEM_BYTES);
        smem_set = 1;
    }

    prep_gather_kernel<<<4096, 256>>>(inputs, sampled, kern);
    prep_bcorr_kernel<<<PS / 256, 256>>>(sampled, bias);
    prep_true_kernel<<<PN / 8, 256>>>(inputs, targets, kern, bias);

    dim3 grid(PS / 128, PN / 128);
    gemm_exp_kernel<<<grid, 256, SMEM_BYTES>>>(targets, sampled);

    finalize_kernel<<<1, 1024>>>(out);
}